// round 11
// baseline (speedup 1.0000x reference)
#include <cuda_runtime.h>
#include <cuda_bf16.h>

#define B_FIXED  4096
#define D_FIXED  256
#define MAX_GAP  5
#define LOSS_W   0.1
#define NBLK     128
#define NTHR     512
#define NWARP    (NTHR / 32)            // 16
#define NBINS    16384                  // key = (vid<<10) | frame
#define NCW      (NBINS / 4)            // packed byte counters, 4 bins/word
#define PAIR_CAP 2048
#define OVF_CAP  256
#define POS_PER_BLK (B_FIXED / NBLK)    // 32

__device__ double       g_ploss[NBLK];
__device__ unsigned int g_pcnt[NBLK];
__device__ unsigned int g_done;

// Dynamic smem (~89 KB):
//   u32 cnt [NCW]       16 KB  (byte counters, zeroed each launch)
//   u32 pairs[PAIR_CAP]  8 KB
//   u32 ovf [OVF_CAP]    1 KB  (bin<<12 | id)
//   u16 ids [NBINS*2]   64 KB  (2 slots/bin; validated by cnt, never zeroed)
#define SMEM_BYTES (NCW*4 + PAIR_CAP*4 + OVF_CAP*4 + NBINS*2*2)

__device__ __forceinline__ unsigned int cnt_byte(const unsigned int* cnt, int k)
{
    return (cnt[k >> 2] >> ((k & 3) * 8)) & 0xFFu;
}

__global__ void __launch_bounds__(NTHR)
main_kernel(const float* __restrict__ emb,
            const int*   __restrict__ frames,
            const int*   __restrict__ vids,
            float*       __restrict__ out)
{
    extern __shared__ unsigned int smem_raw[];
    unsigned int*   cnt   = smem_raw;
    unsigned int*   pairs = cnt + NCW;
    unsigned int*   ovf   = pairs + PAIR_CAP;
    unsigned short* ids   = (unsigned short*)(ovf + OVF_CAP);

    __shared__ int          s_np;
    __shared__ int          s_novf;
    __shared__ double       s_loss[NWARP];
    __shared__ unsigned int s_cnt[NWARP];
    __shared__ bool         s_last;

    const int tid  = threadIdx.x;
    const int warp = tid >> 5;
    const int lane = tid & 31;

    // ---- 1. zero counters ----
    {
        uint4* c4 = (uint4*)cnt;
        #pragma unroll
        for (int t = tid; t < NCW / 4; t += NTHR)
            c4[t] = make_uint4(0, 0, 0, 0);
    }
    if (tid == 0) { s_np = 0; s_novf = 0; }
    __syncthreads();

    // ---- 2. hash insert: 8 elements per thread ----
    {
        const int4* f4 = (const int4*)frames;
        const int4* v4 = (const int4*)vids;
        #pragma unroll
        for (int g = 0; g < 2; g++) {
            const int t  = tid + g * NTHR;            // int4 group index
            int4 f = __ldg(&f4[t]);
            int4 v = __ldg(&v4[t]);
            int ks[4] = { (v.x << 10) | f.x, (v.y << 10) | f.y,
                          (v.z << 10) | f.z, (v.w << 10) | f.w };
            #pragma unroll
            for (int u = 0; u < 4; u++) {
                const int k  = ks[u];
                const int e  = t * 4 + u;
                const int sh = (k & 3) * 8;
                unsigned int prev = atomicAdd(&cnt[k >> 2], 1u << sh);
                int slot = (int)((prev >> sh) & 0xFFu);
                if (slot < 2) {
                    ids[k * 2 + slot] = (unsigned short)e;
                } else {
                    int o = atomicAdd(&s_novf, 1);
                    if (o < OVF_CAP)
                        ovf[o] = ((unsigned int)k << 12) | (unsigned int)e;
                }
            }
        }
    }
    __syncthreads();

    // ---- 3. probe: block owns elements [blockIdx*32, +32) ----
    if (tid < POS_PER_BLK) {
        const int e = blockIdx.x * POS_PER_BLK + tid;
        const int k = (__ldg(&vids[e]) << 10) | __ldg(&frames[e]);
        const int novf = min(s_novf, OVF_CAP);

        // df = 1..5: pair with EVERY entry of bin k+df (lower frame probes up;
        // k+df stays within this vid since frame <= 999 < 1024-5)
        #pragma unroll
        for (int df = 1; df <= MAX_GAP; df++) {
            const int kb = k + df;
            const unsigned int c = cnt_byte(cnt, kb);
            if (c == 0) continue;
            {
                int idx = atomicAdd(&s_np, 1);
                pairs[idx] = ((unsigned int)df << 24) | ((unsigned int)e << 12)
                           | (unsigned int)ids[kb * 2];
            }
            if (c >= 2) {
                int idx = atomicAdd(&s_np, 1);
                pairs[idx] = ((unsigned int)df << 24) | ((unsigned int)e << 12)
                           | (unsigned int)ids[kb * 2 + 1];
            }
            if (c > 2) {
                for (int o = 0; o < novf; o++) {
                    unsigned int w = ovf[o];
                    if ((int)(w >> 12) == kb) {
                        int idx = atomicAdd(&s_np, 1);
                        pairs[idx] = ((unsigned int)df << 24)
                                   | ((unsigned int)e << 12) | (w & 0xFFFu);
                    }
                }
            }
        }

        // df = 0: INDEX-ordered within-bin pairs. e pairs with every bin-mate x
        // having index(x) < index(e) -> each unordered pair emitted exactly
        // once, by the larger index. No slot bookkeeping needed.
        const unsigned int c0 = cnt_byte(cnt, k);
        if (c0 >= 2) {
            const int i0 = (int)ids[k * 2];
            const int i1 = (int)ids[k * 2 + 1];
            if (i0 < e) {
                int idx = atomicAdd(&s_np, 1);
                pairs[idx] = ((unsigned int)e << 12) | (unsigned int)i0;
            }
            if (i1 < e) {
                int idx = atomicAdd(&s_np, 1);
                pairs[idx] = ((unsigned int)e << 12) | (unsigned int)i1;
            }
            if (c0 > 2) {
                for (int o = 0; o < novf; o++) {
                    unsigned int w = ovf[o];
                    if ((int)(w >> 12) == k && (int)(w & 0xFFFu) < e) {
                        int idx = atomicAdd(&s_np, 1);
                        pairs[idx] = ((unsigned int)e << 12) | (w & 0xFFFu);
                    }
                }
            }
        }
    }
    __syncthreads();

    // ---- 4. drain: one warp per pair ----
    double       loss = 0.0;
    unsigned int cnt_acc = 0;
    {
        const int np = min(s_np, PAIR_CAP);
        for (int p = warp; p < np; p += NWARP) {
            const unsigned int pk = pairs[p];
            const int df = pk >> 24;
            const int i  = (pk >> 12) & 0xFFF;
            const int j  = pk & 0xFFF;
            const float4* ri = (const float4*)(emb + (size_t)i * D_FIXED);
            const float4* rj = (const float4*)(emb + (size_t)j * D_FIXED);

            float4 a0 = __ldg(&ri[lane]);        float4 b0 = __ldg(&rj[lane]);
            float4 a1 = __ldg(&ri[lane + 32]);   float4 b1 = __ldg(&rj[lane + 32]);

            float d0 = a0.x - b0.x, d1 = a0.y - b0.y;
            float d2 = a0.z - b0.z, d3 = a0.w - b0.w;
            float acc = d0 * d0;
            acc = fmaf(d1, d1, acc); acc = fmaf(d2, d2, acc); acc = fmaf(d3, d3, acc);
            d0 = a1.x - b1.x; d1 = a1.y - b1.y; d2 = a1.z - b1.z; d3 = a1.w - b1.w;
            acc = fmaf(d0, d0, acc); acc = fmaf(d1, d1, acc);
            acc = fmaf(d2, d2, acc); acc = fmaf(d3, d3, acc);

            #pragma unroll
            for (int off = 16; off > 0; off >>= 1)
                acc += __shfl_down_sync(0xFFFFFFFFu, acc, off);

            if (lane == 0) {
                float w = 1.0f / (1.0f + (float)df);
                loss += (double)(acc * w * (1.0f / (float)D_FIXED));
                cnt_acc += 1u;
            }
        }
    }

    // ---- 5. block reduction ----
    #pragma unroll
    for (int off = 16; off > 0; off >>= 1) {
        loss    += __shfl_down_sync(0xFFFFFFFFu, loss, off);
        cnt_acc += __shfl_down_sync(0xFFFFFFFFu, cnt_acc, off);
    }
    if (lane == 0) { s_loss[warp] = loss; s_cnt[warp] = cnt_acc; }
    __syncthreads();

    if (warp == 0) {
        double       l = (lane < NWARP) ? s_loss[lane] : 0.0;
        unsigned int c = (lane < NWARP) ? s_cnt[lane]  : 0u;
        #pragma unroll
        for (int off = 8; off > 0; off >>= 1) {
            l += __shfl_down_sync(0xFFFFFFFFu, l, off);
            c += __shfl_down_sync(0xFFFFFFFFu, c, off);
        }
        if (lane == 0) { g_ploss[blockIdx.x] = l; g_pcnt[blockIdx.x] = c; }
    }

    // ---- 6. last-block-done grid reduction ----
    __threadfence();
    if (tid == 0) {
        unsigned int prev = atomicAdd(&g_done, 1u);
        s_last = (prev == NBLK - 1);
    }
    __syncthreads();

    if (s_last) {
        __threadfence();
        double       l = (tid < NBLK) ? g_ploss[tid] : 0.0;
        unsigned int c = (tid < NBLK) ? g_pcnt[tid]  : 0u;
        #pragma unroll
        for (int off = 16; off > 0; off >>= 1) {
            l += __shfl_down_sync(0xFFFFFFFFu, l, off);
            c += __shfl_down_sync(0xFFFFFFFFu, c, off);
        }
        if (lane == 0) { s_loss[warp] = l; s_cnt[warp] = c; }
        __syncthreads();
        if (tid == 0) {
            double L = 0.0; unsigned int C = 0u;
            #pragma unroll
            for (int w = 0; w < NWARP; w++) { L += s_loss[w]; C += s_cnt[w]; }
            double Cd = (double)C;
            if (Cd < 1.0) Cd = 1.0;
            out[0] = (float)(LOSS_W * L / Cd);
            g_done = 0;
        }
    }
}

// ---------------------------------------------------------------------------
extern "C" void kernel_launch(void* const* d_in, const int* in_sizes, int n_in,
                              void* d_out, int out_size)
{
    const float* emb    = (const float*)d_in[0];
    const int*   frames = (const int*)d_in[1];
    const int*   vids   = (const int*)d_in[2];
    float*       out    = (float*)d_out;

    static bool attr_set = false;
    if (!attr_set) {
        cudaFuncSetAttribute(main_kernel,
                             cudaFuncAttributeMaxDynamicSharedMemorySize,
                             SMEM_BYTES);
        attr_set = true;
    }

    main_kernel<<<NBLK, NTHR, SMEM_BYTES>>>(emb, frames, vids, out);
}